// round 2
// baseline (speedup 1.0000x reference)
#include <cuda_runtime.h>
#include <cuda_fp16.h>
#include <cstdint>

// Problem constants
#define BATCH    8
#define NHEADS   8
#define DHEAD    64
#define SEQ      1024
#define BM       128     // q rows per CTA (8 warps x 16)
#define BN       64      // k cols per inner tile
#define NTHREADS 256
#define NKT      (SEQ / BN)   // 16
#define LDQ      136     // halves per smem row of sQ ([dd][t], t=128 + pad 8)
#define LDK      72      // halves per smem row of sK/sV ([dd][t], t=64 + pad 8)

__device__ __forceinline__ uint32_t packh(__half lo, __half hi) {
    return ((uint32_t)__half_as_ushort(hi) << 16) | (uint32_t)__half_as_ushort(lo);
}
__device__ __forceinline__ uint32_t f2h2(float x, float y) {
    __half2 h = __floats2half2_rn(x, y);
    return *reinterpret_cast<uint32_t*>(&h);
}
__device__ __forceinline__ void mma16816(float* d, const uint32_t* a, uint32_t b0, uint32_t b1) {
    asm volatile(
        "mma.sync.aligned.m16n8k16.row.col.f32.f16.f16.f32 "
        "{%0,%1,%2,%3}, {%4,%5,%6,%7}, {%8,%9}, {%0,%1,%2,%3};\n"
        : "+f"(d[0]), "+f"(d[1]), "+f"(d[2]), "+f"(d[3])
        : "r"(a[0]), "r"(a[1]), "r"(a[2]), "r"(a[3]), "r"(b0), "r"(b1));
}

__global__ __launch_bounds__(NTHREADS, 1)
void mha_flash_kernel(const float* __restrict__ q, const float* __restrict__ k,
                      const float* __restrict__ v, const float* __restrict__ mask,
                      float* __restrict__ out) {
    __shared__ __align__(16) __half sQ[DHEAD * LDQ];
    __shared__ __align__(16) __half sK[DHEAD * LDK];
    __shared__ __align__(16) __half sV[DHEAD * LDK];

    const int qt    = blockIdx.x;   // 0..7 : q tile
    const int bh    = blockIdx.y;   // 0..63
    const int batch = bh >> 3;
    const float* qb = q + (size_t)bh * (DHEAD * SEQ);
    const float* kb = k + (size_t)bh * (DHEAD * SEQ);
    const float* vb = v + (size_t)bh * (DHEAD * SEQ);
    const float* mb = mask + (size_t)batch * SEQ * SEQ;
    float*       ob = out + (size_t)bh * (DHEAD * SEQ);

    const int tid  = threadIdx.x;
    const int warp = tid >> 5;
    const int lane = tid & 31;
    const int g    = lane >> 2;   // 0..7
    const int c4   = lane & 3;    // 0..3

    const int t0 = qt * BM;

    // ---- Load Q tile: gmem [dd][t] fp32 -> smem [dd][t] fp16, fold 0.125 scale (exact) ----
    #pragma unroll
    for (int i = tid; i < DHEAD * (BM / 2); i += NTHREADS) {
        int dd = i >> 6;          // BM/2 = 64 float2 per row
        int t2 = i & 63;
        float2 val = *reinterpret_cast<const float2*>(qb + (size_t)dd * SEQ + t0 + 2 * t2);
        *reinterpret_cast<__half2*>(&sQ[dd * LDQ + 2 * t2]) =
            __floats2half2_rn(val.x * 0.125f, val.y * 0.125f);
    }

    // ---- Prefetch K/V tile 0 into registers (software pipeline stage) ----
    float2 rk[8], rv[8];
    {
        const int kbase = 0;
        #pragma unroll
        for (int u = 0; u < 8; u++) {
            int i = tid + u * NTHREADS;
            int dd = i >> 5;
            int t2 = i & 31;
            rk[u] = *reinterpret_cast<const float2*>(kb + (size_t)dd * SEQ + kbase + 2 * t2);
            rv[u] = *reinterpret_cast<const float2*>(vb + (size_t)dd * SEQ + kbase + 2 * t2);
        }
    }

    __syncthreads();

    // ---- Q A-fragments (row-major A of m16n8k16), kept in registers for whole loop ----
    const int r0 = warp * 16 + g;   // within tile
    const int r8 = r0 + 8;
    uint32_t aq[4][4];
    #pragma unroll
    for (int kk = 0; kk < 4; kk++) {
        int col = 16 * kk + 2 * c4;
        aq[kk][0] = packh(sQ[(col    ) * LDQ + r0], sQ[(col + 1) * LDQ + r0]);
        aq[kk][1] = packh(sQ[(col    ) * LDQ + r8], sQ[(col + 1) * LDQ + r8]);
        aq[kk][2] = packh(sQ[(col + 8) * LDQ + r0], sQ[(col + 9) * LDQ + r0]);
        aq[kk][3] = packh(sQ[(col + 8) * LDQ + r8], sQ[(col + 9) * LDQ + r8]);
    }

    // ---- Flash state ----
    float m0 = -1e30f, m8 = -1e30f, l0 = 0.f, l8 = 0.f;
    float o[8][4];
    #pragma unroll
    for (int j = 0; j < 8; j++) { o[j][0] = 0.f; o[j][1] = 0.f; o[j][2] = 0.f; o[j][3] = 0.f; }

    const int qr0 = t0 + r0;
    const int qr8 = t0 + r8;

    for (int kt = 0; kt < NKT; kt++) {
        const int kbase = kt * BN;

        // ---- Publish prefetched K/V tile to smem (fp32 -> fp16) ----
        #pragma unroll
        for (int u = 0; u < 8; u++) {
            int i = tid + u * NTHREADS;
            int dd = i >> 5;
            int t2 = i & 31;
            *reinterpret_cast<__half2*>(&sK[dd * LDK + 2 * t2]) = __floats2half2_rn(rk[u].x, rk[u].y);
            *reinterpret_cast<__half2*>(&sV[dd * LDK + 2 * t2]) = __floats2half2_rn(rv[u].x, rv[u].y);
        }
        __syncthreads();

        // ---- Prefetch next tile while we compute on this one ----
        if (kt + 1 < NKT) {
            const int nbase = kbase + BN;
            #pragma unroll
            for (int u = 0; u < 8; u++) {
                int i = tid + u * NTHREADS;
                int dd = i >> 5;
                int t2 = i & 31;
                rk[u] = *reinterpret_cast<const float2*>(kb + (size_t)dd * SEQ + nbase + 2 * t2);
                rv[u] = *reinterpret_cast<const float2*>(vb + (size_t)dd * SEQ + nbase + 2 * t2);
            }
        }

        // ---- Scores: S = (Q*0.125) @ K^T  (fp32 accum) ----
        float s[8][4];
        #pragma unroll
        for (int j = 0; j < 8; j++) { s[j][0] = 0.f; s[j][1] = 0.f; s[j][2] = 0.f; s[j][3] = 0.f; }

        #pragma unroll
        for (int kk = 0; kk < 4; kk++) {
            int row = 16 * kk + 2 * c4;     // dd index for B fragment
            #pragma unroll
            for (int j = 0; j < 8; j++) {
                int tk = 8 * j + g;
                uint32_t b0 = packh(sK[(row    ) * LDK + tk], sK[(row + 1) * LDK + tk]);
                uint32_t b1 = packh(sK[(row + 8) * LDK + tk], sK[(row + 9) * LDK + tk]);
                mma16816(s[j], aq[kk], b0, b1);
            }
        }

        // ---- Mask (additive {0,-10000} -> drop where != 0) ----
        const float* mrow0 = mb + (size_t)qr0 * SEQ + kbase;
        const float* mrow8 = mb + (size_t)qr8 * SEQ + kbase;
        #pragma unroll
        for (int j = 0; j < 8; j++) {
            int cc = 8 * j + 2 * c4;
            float2 mk0 = *reinterpret_cast<const float2*>(mrow0 + cc);
            float2 mk8 = *reinterpret_cast<const float2*>(mrow8 + cc);
            if (mk0.x != 0.f) s[j][0] = -1e30f;
            if (mk0.y != 0.f) s[j][1] = -1e30f;
            if (mk8.x != 0.f) s[j][2] = -1e30f;
            if (mk8.y != 0.f) s[j][3] = -1e30f;
        }

        // ---- Online softmax (rows r0 and r8) ----
        float vmax0 = -1e30f, vmax8 = -1e30f;
        #pragma unroll
        for (int j = 0; j < 8; j++) {
            vmax0 = fmaxf(vmax0, fmaxf(s[j][0], s[j][1]));
            vmax8 = fmaxf(vmax8, fmaxf(s[j][2], s[j][3]));
        }
        vmax0 = fmaxf(vmax0, __shfl_xor_sync(0xffffffffu, vmax0, 1));
        vmax0 = fmaxf(vmax0, __shfl_xor_sync(0xffffffffu, vmax0, 2));
        vmax8 = fmaxf(vmax8, __shfl_xor_sync(0xffffffffu, vmax8, 1));
        vmax8 = fmaxf(vmax8, __shfl_xor_sync(0xffffffffu, vmax8, 2));

        float mn0 = fmaxf(m0, vmax0);
        float mn8 = fmaxf(m8, vmax8);
        float alpha0 = __expf(m0 - mn0);
        float alpha8 = __expf(m8 - mn8);
        m0 = mn0; m8 = mn8;

        float sum0 = 0.f, sum8 = 0.f;
        #pragma unroll
        for (int j = 0; j < 8; j++) {
            float p0 = (s[j][0] > -1e29f) ? __expf(s[j][0] - mn0) : 0.f;
            float p1 = (s[j][1] > -1e29f) ? __expf(s[j][1] - mn0) : 0.f;
            float p2 = (s[j][2] > -1e29f) ? __expf(s[j][2] - mn8) : 0.f;
            float p3 = (s[j][3] > -1e29f) ? __expf(s[j][3] - mn8) : 0.f;
            sum0 += p0 + p1;
            sum8 += p2 + p3;
            s[j][0] = p0; s[j][1] = p1; s[j][2] = p2; s[j][3] = p3;
        }
        // *** THE FIX: reduce the row-sum across the 4-thread row group ***
        sum0 += __shfl_xor_sync(0xffffffffu, sum0, 1);
        sum0 += __shfl_xor_sync(0xffffffffu, sum0, 2);
        sum8 += __shfl_xor_sync(0xffffffffu, sum8, 1);
        sum8 += __shfl_xor_sync(0xffffffffu, sum8, 2);

        l0 = l0 * alpha0 + sum0;
        l8 = l8 * alpha8 + sum8;
        #pragma unroll
        for (int j = 0; j < 8; j++) {
            o[j][0] *= alpha0; o[j][1] *= alpha0;
            o[j][2] *= alpha8; o[j][3] *= alpha8;
        }

        // ---- P fragments: accumulator layout == A-fragment layout (flash trick) ----
        uint32_t ap[4][4];
        #pragma unroll
        for (int kk = 0; kk < 4; kk++) {
            int j0 = 2 * kk, j1 = 2 * kk + 1;
            ap[kk][0] = f2h2(s[j0][0], s[j0][1]);
            ap[kk][1] = f2h2(s[j0][2], s[j0][3]);
            ap[kk][2] = f2h2(s[j1][0], s[j1][1]);
            ap[kk][3] = f2h2(s[j1][2], s[j1][3]);
        }

        // ---- O += P @ V : V B-fragments are single LDS.32 from sV[dd][t] ----
        #pragma unroll
        for (int kk = 0; kk < 4; kk++) {
            int trow = 16 * kk + 2 * c4;
            #pragma unroll
            for (int j = 0; j < 8; j++) {
                int dd = 8 * j + g;
                uint32_t b0 = *reinterpret_cast<const uint32_t*>(&sV[dd * LDK + trow]);
                uint32_t b1 = *reinterpret_cast<const uint32_t*>(&sV[dd * LDK + trow + 8]);
                mma16816(o[j], ap[kk], b0, b1);
            }
        }
        __syncthreads();
    }

    // ---- Epilogue: out[b][head*64+dd][t] = o / l ----
    float il0 = 1.f / l0;
    float il8 = 1.f / l8;
    #pragma unroll
    for (int j = 0; j < 8; j++) {
        int dd = 8 * j + 2 * c4;
        ob[(size_t)(dd    ) * SEQ + qr0] = o[j][0] * il0;
        ob[(size_t)(dd + 1) * SEQ + qr0] = o[j][1] * il0;
        ob[(size_t)(dd    ) * SEQ + qr8] = o[j][2] * il8;
        ob[(size_t)(dd + 1) * SEQ + qr8] = o[j][3] * il8;
    }
}

extern "C" void kernel_launch(void* const* d_in, const int* in_sizes, int n_in,
                              void* d_out, int out_size) {
    const float* q    = (const float*)d_in[0];
    const float* k    = (const float*)d_in[1];
    const float* v    = (const float*)d_in[2];
    const float* mask = (const float*)d_in[3];
    float* out = (float*)d_out;

    dim3 grid(SEQ / BM, BATCH * NHEADS);   // (8, 64)
    dim3 block(NTHREADS);
    mha_flash_kernel<<<grid, block>>>(q, k, v, mask, out);
}